// round 2
// baseline (speedup 1.0000x reference)
#include <cuda_runtime.h>

#define NQ    14
#define NL    6
#define BATCH 1024
#define NAMP  16384           // 2^14 amplitudes
#define TPB   512             // threads per CTA; each owns 32 amplitudes

// Precomputed per-launch (weights are shared across the batch):
//  d_rot:   6*14 Rot gate matrices, 4 complex entries each [g00,g01,g10,g11]
//  d_qmask: per layer, the composed CNOT-ring permutation Q_l as 14 GF(2) columns:
//           Q_l(x) = XOR over set bits b of x of d_qmask[l*14+b]
//           (state_after[x] = state_before[Q_l(x)])
__device__ float2   d_rot[NL * NQ * 4];
__device__ unsigned d_qmask[NL * NQ];

__device__ __forceinline__ int swz(int x) { return x ^ ((x >> 5) & 31); }

__device__ __forceinline__ float2 cmul(float2 a, float2 b) {
    return make_float2(a.x * b.x - a.y * b.y, a.x * b.y + a.y * b.x);
}

// Apply 2x2 complex gate on local bit P of a 32-amplitude register block.
template <int P>
__device__ __forceinline__ void apply_gate(float2* r, const float2* g) {
    const float2 g00 = g[0], g01 = g[1], g10 = g[2], g11 = g[3];
#pragma unroll
    for (int base = 0; base < 32; base++) {
        if (base & (1 << P)) continue;
        const int hi = base | (1 << P);
        const float2 a = r[base], b = r[hi];
        float2 na, nb;
        na.x = g00.x * a.x - g00.y * a.y + g01.x * b.x - g01.y * b.y;
        na.y = g00.x * a.y + g00.y * a.x + g01.x * b.y + g01.y * b.x;
        nb.x = g10.x * a.x - g10.y * a.y + g11.x * b.x - g11.y * b.y;
        nb.y = g10.x * a.y + g10.y * a.x + g11.x * b.y + g11.y * b.x;
        r[base] = na;
        r[hi]   = nb;
    }
}

// ---------------------------------------------------------------------------
// Setup: Rot matrices + composed CNOT-ring permutations (tiny, 1 block)
// ---------------------------------------------------------------------------
__global__ void setup_kernel(const float* __restrict__ w) {
    const int tid = threadIdx.x;
    if (tid < NL * NQ) {
        // Rot(phi, theta, omega) = RZ(omega) RY(theta) RZ(phi)
        const float phi = w[tid * 3 + 0];
        const float th  = w[tid * 3 + 1];
        const float om  = w[tid * 3 + 2];
        float cth, sth, ca, sa, cb, sb;
        sincosf(0.5f * th, &sth, &cth);
        sincosf(0.5f * (phi + om), &sa, &ca);
        sincosf(0.5f * (phi - om), &sb, &cb);
        d_rot[tid * 4 + 0] = make_float2( cth * ca, -cth * sa);  // g00 = c e^{-i(phi+om)/2}
        d_rot[tid * 4 + 1] = make_float2(-sth * cb, -sth * sb);  // g01 = -s e^{+i(phi-om)/2}
        d_rot[tid * 4 + 2] = make_float2( sth * cb, -sth * sb);  // g10 =  s e^{-i(phi-om)/2}
        d_rot[tid * 4 + 3] = make_float2( cth * ca,  cth * sa);  // g11 = c e^{+i(phi+om)/2}
    } else if (tid >= 128 && tid < 128 + NL * NQ) {
        // Column b of Q_l: push e_b through CNOTs applied w = 13 .. 0 (innermost first)
        const int id = tid - 128;
        const int l = id / NQ, b = id % NQ;
        const int rr = (l % (NQ - 1)) + 1;
        unsigned y = 1u << b;
        for (int ww = NQ - 1; ww >= 0; ww--) {
            const unsigned bit = (y >> ww) & 1u;
            y ^= bit << ((ww + rr) % NQ);
        }
        d_qmask[id] = y;
    }
}

// ---------------------------------------------------------------------------
// Main simulation: one batch element per CTA, state in 128 KB shared memory
// ---------------------------------------------------------------------------
__global__ void __launch_bounds__(TPB, 1)
qsim_kernel(const float* __restrict__ xin, float* __restrict__ out) {
    extern __shared__ float2 s[];                 // 16384 amplitudes (swizzled)
    __shared__ float2   rotsh[NL * NQ * 4];
    __shared__ unsigned qmsh[NL * NQ];
    __shared__ float2   rxf[NQ];                  // (cos x/2, sin x/2) per wire
    __shared__ float    red[TPB / 32];

    const int t = threadIdx.x;
    const int b = blockIdx.x;

    for (int i = t; i < NL * NQ * 4; i += TPB) rotsh[i] = d_rot[i];
    if (t < NL * NQ) qmsh[t] = d_qmask[t];
    if (t < NQ) {
        float c, sn;
        sincosf(0.5f * xin[b * NQ + t], &sn, &c);
        rxf[t] = make_float2(c, sn);
    }
    __syncthreads();

    float2 r[32];

    // ---- init: RX-encoded product state, directly in P1 layout x=(t<<5)|j ----
    // RX factor: bit=0 -> (c,0), bit=1 -> (0,-s)
    {
        float2 pre = make_float2(1.f, 0.f);
#pragma unroll
        for (int k = 0; k < 9; k++) {
            const float2 f = ((t >> k) & 1) ? make_float2(0.f, -rxf[5 + k].y)
                                            : make_float2(rxf[5 + k].x, 0.f);
            pre = cmul(pre, f);
        }
#pragma unroll
        for (int j = 0; j < 32; j++) {
            float2 v = pre;
#pragma unroll
            for (int k = 0; k < 5; k++) {
                const float2 f = ((j >> k) & 1) ? make_float2(0.f, -rxf[k].y)
                                                : make_float2(rxf[k].x, 0.f);
                v = cmul(v, f);
            }
            r[j] = v;
        }
    }

    for (int l = 0; l < NL; l++) {
        const float2* G = &rotsh[l * NQ * 4];

        // ---- P1: wires 0..4 local; read = gather through previous layer's CNOT perm
        if (l > 0) {
            const unsigned* qm = &qmsh[(l - 1) * NQ];
            unsigned base = 0;
#pragma unroll
            for (int k = 0; k < 9; k++)
                if ((t >> k) & 1) base ^= qm[5 + k];
            const unsigned q0 = qm[0], q1 = qm[1], q2 = qm[2], q3 = qm[3], q4 = qm[4];
#pragma unroll
            for (int j = 0; j < 32; j++) {
                unsigned idx = base;
                if (j & 1)  idx ^= q0;
                if (j & 2)  idx ^= q1;
                if (j & 4)  idx ^= q2;
                if (j & 8)  idx ^= q3;
                if (j & 16) idx ^= q4;
                r[j] = s[swz(idx)];
            }
        }
        apply_gate<0>(r, G + 0 * 4);
        apply_gate<1>(r, G + 1 * 4);
        apply_gate<2>(r, G + 2 * 4);
        apply_gate<3>(r, G + 3 * 4);
        apply_gate<4>(r, G + 4 * 4);
        if (l > 0) __syncthreads();   // all gather-reads done before overwriting
#pragma unroll
        for (int j = 0; j < 32; j++) s[swz((t << 5) | j)] = r[j];
        __syncthreads();

        // ---- P2: wires 5..9 local;  x = t[8:5]<<10 | j<<5 | t[4:0]
        {
            const int xb = ((t >> 5) << 10) | (t & 31);
#pragma unroll
            for (int j = 0; j < 32; j++) r[j] = s[swz(xb | (j << 5))];
            apply_gate<0>(r, G + 5 * 4);
            apply_gate<1>(r, G + 6 * 4);
            apply_gate<2>(r, G + 7 * 4);
            apply_gate<3>(r, G + 8 * 4);
            apply_gate<4>(r, G + 9 * 4);
#pragma unroll
            for (int j = 0; j < 32; j++) s[swz(xb | (j << 5))] = r[j];
            __syncthreads();
        }

        // ---- P3: wires 10..13 at local bits 1..4;  x = j[4:1]<<10 | t<<1 | j[0]
        {
            const int tb = t << 1;
#pragma unroll
            for (int j = 0; j < 32; j++) {
                const int x = ((j >> 1) << 10) | tb | (j & 1);
                r[j] = s[swz(x)];
            }
            apply_gate<1>(r, G + 10 * 4);
            apply_gate<2>(r, G + 11 * 4);
            apply_gate<3>(r, G + 12 * 4);
            apply_gate<4>(r, G + 13 * 4);
#pragma unroll
            for (int j = 0; j < 32; j++) {
                const int x = ((j >> 1) << 10) | tb | (j & 1);
                s[swz(x)] = r[j];
            }
            __syncthreads();
        }
    }

    // ---- reduction: <Z0> with the final CNOT layer folded in as a gather ----
    {
        const unsigned* qm = &qmsh[(NL - 1) * NQ];
        unsigned base = 0;
#pragma unroll
        for (int k = 0; k < 9; k++)
            if ((t >> k) & 1) base ^= qm[5 + k];
        const unsigned q0 = qm[0], q1 = qm[1], q2 = qm[2], q3 = qm[3], q4 = qm[4];
        float acc = 0.f;
#pragma unroll
        for (int j = 0; j < 32; j++) {
            unsigned idx = base;
            if (j & 1)  idx ^= q0;
            if (j & 2)  idx ^= q1;
            if (j & 4)  idx ^= q2;
            if (j & 8)  idx ^= q3;
            if (j & 16) idx ^= q4;
            const float2 v = s[swz(idx)];
            const float p = v.x * v.x + v.y * v.y;
            acc += (j & 1) ? -p : p;   // x bit0 = wire 0
        }
#pragma unroll
        for (int off = 16; off; off >>= 1)
            acc += __shfl_xor_sync(0xFFFFFFFFu, acc, off);
        if ((t & 31) == 0) red[t >> 5] = acc;
        __syncthreads();
        if (t == 0) {
            float tot = 0.f;
#pragma unroll
            for (int i = 0; i < TPB / 32; i++) tot += red[i];
            out[b] = tot;
        }
    }
}

extern "C" void kernel_launch(void* const* d_in, const int* in_sizes, int n_in,
                              void* d_out, int out_size) {
    const float* x = (const float*)d_in[0];       // (1024, 14)
    const float* w = (const float*)d_in[1];       // (6, 14, 3)
    float* out = (float*)d_out;                   // (1024,)

    cudaFuncSetAttribute(qsim_kernel,
                         cudaFuncAttributeMaxDynamicSharedMemorySize,
                         NAMP * sizeof(float2));

    setup_kernel<<<1, 256>>>(w);
    qsim_kernel<<<BATCH, TPB, NAMP * sizeof(float2)>>>(x, out);
}